// round 3
// baseline (speedup 1.0000x reference)
#include <cuda_runtime.h>
#include <cuda_bf16.h>
#include <cfloat>

// ColorReducer: out[b,:,h,w] = palette[argmin_k ||x[b,:,h,w] - palette[k]||^2]
// argmin_k ||p-c||^2 == argmax_k s_k, s_k = p.c - 0.5*||c||^2.
//
// Round-3 strategy:
//  - fma.rn.f32x2 packed FMA (2 pixels per instruction, bit-identical to FFMA.rn)
//  - 8 pixels per thread: palette LDS amortized 2x better (L1 crossbar was the
//    round-2 bottleneck at 71.4%)
//  - tournament argmax over groups of 4 colors; winning group's scores recomputed
//    at the end with identical FMA order => exact equality match, first-index ties.

#define CR_HW 262144
#define PPT 8   // pixels per thread

#define F2FMA(d, a, b, c) \
    asm("fma.rn.f32x2 %0, %1, %2, %3;" : "=l"(d) : "l"(a), "l"(b), "l"(c))
#define F2PACK(d, lo, hi) \
    asm("mov.b64 %0, {%1, %2};" : "=l"(d) : "f"(lo), "f"(hi))
#define F2UNPACK(lo, hi, v) \
    asm("mov.b64 {%0, %1}, %2;" : "=f"(lo), "=f"(hi) : "l"(v))

typedef unsigned long long ull;

__global__ void __launch_bounds__(256)
color_reduce_f2_kernel(const float* __restrict__ x,
                       const float* __restrict__ pal,
                       float* __restrict__ out,
                       int npix)
{
    // duplicated palette for packed math: [k] = cx,cx,cy,cy,cz,cz,h,h
    __shared__ __align__(16) float spal2f[64][8];
    // compact palette for finale / gather: [k] = {cx,cy,cz,h}
    __shared__ float4 spalc[64];

    int t = threadIdx.x;
    if (t < 64) {
        float cx = pal[t * 3 + 0];
        float cy = pal[t * 3 + 1];
        float cz = pal[t * 3 + 2];
        float h  = -0.5f * (cx * cx + cy * cy + cz * cz);
        spal2f[t][0] = cx; spal2f[t][1] = cx;
        spal2f[t][2] = cy; spal2f[t][3] = cy;
        spal2f[t][4] = cz; spal2f[t][5] = cz;
        spal2f[t][6] = h;  spal2f[t][7] = h;
        spalc[t] = make_float4(cx, cy, cz, h);
    }
    __syncthreads();

    int gid = blockIdx.x * blockDim.x + t;
    int i0  = gid * PPT;
    if (i0 >= npix) return;

    int b = i0 >> 18;             // / CR_HW
    int q = i0 & (CR_HW - 1);

    const float* base  = x   + (size_t)b * 3 * CR_HW + q;
    float*       obase = out + (size_t)b * 3 * CR_HW + q;

    if (i0 + PPT - 1 < npix) {
        // 8 pixels: two float4 per channel plane
        float4 pr0 = *reinterpret_cast<const float4*>(base);
        float4 pr1 = *reinterpret_cast<const float4*>(base + 4);
        float4 pg0 = *reinterpret_cast<const float4*>(base + CR_HW);
        float4 pg1 = *reinterpret_cast<const float4*>(base + CR_HW + 4);
        float4 pb0 = *reinterpret_cast<const float4*>(base + 2 * CR_HW);
        float4 pb1 = *reinterpret_cast<const float4*>(base + 2 * CR_HW + 4);

        float rr[PPT] = {pr0.x, pr0.y, pr0.z, pr0.w, pr1.x, pr1.y, pr1.z, pr1.w};
        float gg[PPT] = {pg0.x, pg0.y, pg0.z, pg0.w, pg1.x, pg1.y, pg1.z, pg1.w};
        float bb[PPT] = {pb0.x, pb0.y, pb0.z, pb0.w, pb1.x, pb1.y, pb1.z, pb1.w};

        // packed pixel pairs per channel: 4 pairs each
        ull rp[4], gp[4], bp[4];
#pragma unroll
        for (int pp = 0; pp < 4; pp++) {
            F2PACK(rp[pp], rr[2 * pp], rr[2 * pp + 1]);
            F2PACK(gp[pp], gg[2 * pp], gg[2 * pp + 1]);
            F2PACK(bp[pp], bb[2 * pp], bb[2 * pp + 1]);
        }

        float best[PPT];
        int   bgrp[PPT];
#pragma unroll
        for (int p = 0; p < PPT; p++) { best[p] = -FLT_MAX; bgrp[p] = 0; }

#pragma unroll 4
        for (int g = 0; g < 16; g++) {
            // load 4 colors' packed palette once, reuse across all 8 pixels
            ull cxx[4], cyy[4], czz[4], chh[4];
#pragma unroll
            for (int c = 0; c < 4; c++) {
                const ulonglong2* pp2 = reinterpret_cast<const ulonglong2*>(spal2f[g * 4 + c]);
                ulonglong2 v0 = pp2[0];
                ulonglong2 v1 = pp2[1];
                cxx[c] = v0.x; cyy[c] = v0.y; czz[c] = v1.x; chh[c] = v1.y;
            }
#pragma unroll
            for (int pp = 0; pp < 4; pp++) {       // 4 pixel pairs
                float s[4][2];                     // [color][pixel-in-pair]
#pragma unroll
                for (int c = 0; c < 4; c++) {
                    ull sv;
                    F2FMA(sv, bp[pp], czz[c], chh[c]);
                    F2FMA(sv, gp[pp], cyy[c], sv);
                    F2FMA(sv, rp[pp], cxx[c], sv);
                    F2UNPACK(s[c][0], s[c][1], sv);
                }
#pragma unroll
                for (int half = 0; half < 2; half++) {
                    int p = 2 * pp + half;
                    float m = fmaxf(fmaxf(s[0][half], s[1][half]),
                                    fmaxf(s[2][half], s[3][half]));
                    if (m > best[p]) { best[p] = m; bgrp[p] = g; }
                }
            }
        }

        // finale: recompute winning group's 4 scores (bit-identical FMA order),
        // pick first index equal to the max, gather its color.
        float4 cc[PPT];
#pragma unroll
        for (int p = 0; p < PPT; p++) {
            int k0 = bgrp[p] * 4;
            float4 c0 = spalc[k0 + 0];
            float4 c1 = spalc[k0 + 1];
            float4 c2 = spalc[k0 + 2];
            float4 c3 = spalc[k0 + 3];
            float px = rr[p], py = gg[p], pz = bb[p];
            float s0 = fmaf(px, c0.x, fmaf(py, c0.y, fmaf(pz, c0.z, c0.w)));
            float s1 = fmaf(px, c1.x, fmaf(py, c1.y, fmaf(pz, c1.z, c1.w)));
            float s2 = fmaf(px, c2.x, fmaf(py, c2.y, fmaf(pz, c2.z, c2.w)));
            float s3 = fmaf(px, c3.x, fmaf(py, c3.y, fmaf(pz, c3.z, c3.w)));
            int j = 3;
            if (s2 == best[p]) j = 2;
            if (s1 == best[p]) j = 1;
            if (s0 == best[p]) j = 0;
            cc[p] = spalc[k0 + j];
        }

        *reinterpret_cast<float4*>(obase) =
            make_float4(cc[0].x, cc[1].x, cc[2].x, cc[3].x);
        *reinterpret_cast<float4*>(obase + 4) =
            make_float4(cc[4].x, cc[5].x, cc[6].x, cc[7].x);
        *reinterpret_cast<float4*>(obase + CR_HW) =
            make_float4(cc[0].y, cc[1].y, cc[2].y, cc[3].y);
        *reinterpret_cast<float4*>(obase + CR_HW + 4) =
            make_float4(cc[4].y, cc[5].y, cc[6].y, cc[7].y);
        *reinterpret_cast<float4*>(obase + 2 * CR_HW) =
            make_float4(cc[0].z, cc[1].z, cc[2].z, cc[3].z);
        *reinterpret_cast<float4*>(obase + 2 * CR_HW + 4) =
            make_float4(cc[4].z, cc[5].z, cc[6].z, cc[7].z);
    } else {
        // scalar tail (not hit for 512x512x8 shapes)
        for (int i = i0; i < npix; i++) {
            int b2 = i >> 18;
            int q2 = i & (CR_HW - 1);
            const float* pb2 = x + (size_t)b2 * 3 * CR_HW + q2;
            float px = pb2[0], py = pb2[CR_HW], pz = pb2[2 * CR_HW];
            float bestv = -FLT_MAX; int bk = 0;
            for (int k = 0; k < 64; k++) {
                float4 c = spalc[k];
                float s = fmaf(px, c.x, fmaf(py, c.y, fmaf(pz, c.z, c.w)));
                if (s > bestv) { bestv = s; bk = k; }
            }
            float4 c = spalc[bk];
            float* ob = out + (size_t)b2 * 3 * CR_HW + q2;
            ob[0] = c.x; ob[CR_HW] = c.y; ob[2 * CR_HW] = c.z;
        }
    }
}

// generic fallback (any shape / ncol) — simple, correct, only used off the fast path
__global__ void color_reduce_generic_kernel(const float* __restrict__ x,
                                            const float* __restrict__ pal,
                                            float* __restrict__ out,
                                            int npix, int hw, int ncol)
{
    extern __shared__ float4 gpal[];
    int t = threadIdx.x;
    for (int k = t; k < ncol; k += blockDim.x) {
        float cx = pal[k * 3 + 0], cy = pal[k * 3 + 1], cz = pal[k * 3 + 2];
        gpal[k] = make_float4(cx, cy, cz, -0.5f * (cx * cx + cy * cy + cz * cz));
    }
    __syncthreads();
    int i = blockIdx.x * blockDim.x + t;
    if (i >= npix) return;
    int b = i / hw, q = i - b * hw;
    const float* pb = x + (size_t)b * 3 * (size_t)hw + q;
    float px = pb[0], py = pb[hw], pz = pb[2 * hw];
    float bestv = -FLT_MAX; int bk = 0;
    for (int k = 0; k < ncol; k++) {
        float4 c = gpal[k];
        float s = fmaf(px, c.x, fmaf(py, c.y, fmaf(pz, c.z, c.w)));
        if (s > bestv) { bestv = s; bk = k; }
    }
    float4 c = gpal[bk];
    float* ob = out + (size_t)b * 3 * (size_t)hw + q;
    ob[0] = c.x; ob[hw] = c.y; ob[2 * hw] = c.z;
}

extern "C" void kernel_launch(void* const* d_in, const int* in_sizes, int n_in,
                              void* d_out, int out_size)
{
    const float* x   = (const float*)d_in[0];
    const float* pal = (const float*)d_in[1];
    float*       out = (float*)d_out;

    int nelem = in_sizes[0];
    int ncol  = in_sizes[1] / 3;
    int npix  = nelem / 3;

    if (ncol == 64 && nelem % (3 * CR_HW) == 0) {
        int threads = 256;
        int groups  = (npix + PPT - 1) / PPT;
        int blocks  = (groups + threads - 1) / threads;
        color_reduce_f2_kernel<<<blocks, threads>>>(x, pal, out, npix);
    } else {
        int hw = npix;  // treat as single batch
        if (nelem % (3 * CR_HW) == 0) hw = CR_HW;
        int threads = 256;
        int blocks  = (npix + threads - 1) / threads;
        color_reduce_generic_kernel<<<blocks, threads, ncol * sizeof(float4)>>>(
            x, pal, out, npix, hw, ncol);
    }
}

// round 4
// speedup vs baseline: 1.2844x; 1.2844x over previous
#include <cuda_runtime.h>
#include <cuda_bf16.h>
#include <cfloat>

// ColorReducer: out[b,:,h,w] = palette[argmin_k ||x[b,:,h,w] - palette[k]||^2]
// argmin_k ||p-c||^2 == argmax_k s_k, s_k = p.c - 0.5*||c||^2.
//
// Round-4 strategy:
//  - palette moved to __constant__ memory (prep kernel -> memcpyToSymbolAsync D2D,
//    graph-capturable). Inner loop reads via the constant port (LDCU/LDC) =>
//    zero L1/shared-crossbar traffic and no 29-cyc LDS latency chains.
//  - fma.rn.f32x2 packed FMA (2 pixels per instruction, bit-identical FFMA.rn)
//  - tournament argmax over groups of 4 colors; winning group's scores recomputed
//    from smem copy of the SAME constant bits => exact equality, first-index ties.

#define CR_HW 262144
#define PPT 4

#define F2FMA(d, a, b, c) \
    asm("fma.rn.f32x2 %0, %1, %2, %3;" : "=l"(d) : "l"(a), "l"(b), "l"(c))
#define F2PACK(d, lo, hi) \
    asm("mov.b64 %0, {%1, %2};" : "=l"(d) : "f"(lo), "f"(hi))
#define F2UNPACK(lo, hi, v) \
    asm("mov.b64 {%0, %1}, %2;" : "=f"(lo), "=f"(hi) : "l"(v))

typedef unsigned long long ull;

// constant-bank palette: [k][0] = {cx,cx},{cy,cy}; [k][1] = {cz,cz},{h,h}
__constant__ __align__(16) ulonglong2 c_pal2[64][2];
__constant__ __align__(16) float4     c_palc[64];

// staging buffers written by prep kernel, memcpy'd into the constant banks
__device__ __align__(16) ulonglong2 g_stage2[64][2];
__device__ __align__(16) float4     g_stagec[64];

__global__ void prep_kernel(const float* __restrict__ pal)
{
    int t = threadIdx.x;
    if (t < 64) {
        float cx = pal[t * 3 + 0];
        float cy = pal[t * 3 + 1];
        float cz = pal[t * 3 + 2];
        float h  = -0.5f * (cx * cx + cy * cy + cz * cz);
        ull uxx, uyy, uzz, uhh;
        F2PACK(uxx, cx, cx);
        F2PACK(uyy, cy, cy);
        F2PACK(uzz, cz, cz);
        F2PACK(uhh, h,  h);
        g_stage2[t][0] = make_ulonglong2(uxx, uyy);
        g_stage2[t][1] = make_ulonglong2(uzz, uhh);
        g_stagec[t]    = make_float4(cx, cy, cz, h);
    }
}

__global__ void __launch_bounds__(256)
color_reduce_c_kernel(const float* __restrict__ x,
                      float* __restrict__ out,
                      int npix)
{
    // smem copy of the compact palette (same bits as constants) for the
    // divergent-index finale + gather only.
    __shared__ float4 spalc[64];
    int t = threadIdx.x;
    if (t < 64) spalc[t] = c_palc[t];
    __syncthreads();

    int gid = blockIdx.x * blockDim.x + t;
    int i0  = gid * PPT;
    if (i0 >= npix) return;

    int b = i0 >> 18;             // / CR_HW
    int q = i0 & (CR_HW - 1);

    const float* base  = x   + (size_t)b * 3 * CR_HW + q;
    float*       obase = out + (size_t)b * 3 * CR_HW + q;

    if (i0 + PPT - 1 < npix) {
        float4 pr = *reinterpret_cast<const float4*>(base);
        float4 pg = *reinterpret_cast<const float4*>(base + CR_HW);
        float4 pb = *reinterpret_cast<const float4*>(base + 2 * CR_HW);

        float rr[4] = {pr.x, pr.y, pr.z, pr.w};
        float gg[4] = {pg.x, pg.y, pg.z, pg.w};
        float bb[4] = {pb.x, pb.y, pb.z, pb.w};

        ull r01, r23, g01, g23, b01, b23;
        F2PACK(r01, rr[0], rr[1]); F2PACK(r23, rr[2], rr[3]);
        F2PACK(g01, gg[0], gg[1]); F2PACK(g23, gg[2], gg[3]);
        F2PACK(b01, bb[0], bb[1]); F2PACK(b23, bb[2], bb[3]);

        ull rp[2] = {r01, r23};
        ull gp[2] = {g01, g23};
        ull bp[2] = {b01, b23};

        float best[4];
        int   bgrp[4];
#pragma unroll
        for (int p = 0; p < 4; p++) { best[p] = -FLT_MAX; bgrp[p] = 0; }

#pragma unroll
        for (int g = 0; g < 16; g++) {
            // palette for 4 colors, loaded once from the constant bank
            // (immediate addresses -> LDCU on the uniform-const port)
            ull cxx[4], cyy[4], czz[4], chh[4];
#pragma unroll
            for (int c = 0; c < 4; c++) {
                ulonglong2 v0 = c_pal2[g * 4 + c][0];
                ulonglong2 v1 = c_pal2[g * 4 + c][1];
                cxx[c] = v0.x; cyy[c] = v0.y; czz[c] = v1.x; chh[c] = v1.y;
            }
#pragma unroll
            for (int pp = 0; pp < 2; pp++) {   // 2 pixel pairs
                float s[4][2];
#pragma unroll
                for (int c = 0; c < 4; c++) {
                    ull sv;
                    F2FMA(sv, bp[pp], czz[c], chh[c]);
                    F2FMA(sv, gp[pp], cyy[c], sv);
                    F2FMA(sv, rp[pp], cxx[c], sv);
                    F2UNPACK(s[c][0], s[c][1], sv);
                }
#pragma unroll
                for (int half = 0; half < 2; half++) {
                    int p = 2 * pp + half;
                    float m = fmaxf(fmaxf(s[0][half], s[1][half]),
                                    fmaxf(s[2][half], s[3][half]));
                    if (m > best[p]) { best[p] = m; bgrp[p] = g; }
                }
            }
        }

        // finale: recompute winning group's 4 scores (identical FMA order ->
        // exact equality), pick first matching index, gather color from smem.
        float4 cc[4];
#pragma unroll
        for (int p = 0; p < 4; p++) {
            int k0 = bgrp[p] * 4;
            float4 c0 = spalc[k0 + 0];
            float4 c1 = spalc[k0 + 1];
            float4 c2 = spalc[k0 + 2];
            float4 c3 = spalc[k0 + 3];
            float px = rr[p], py = gg[p], pz = bb[p];
            float s0 = fmaf(px, c0.x, fmaf(py, c0.y, fmaf(pz, c0.z, c0.w)));
            float s1 = fmaf(px, c1.x, fmaf(py, c1.y, fmaf(pz, c1.z, c1.w)));
            float s2 = fmaf(px, c2.x, fmaf(py, c2.y, fmaf(pz, c2.z, c2.w)));
            float s3 = fmaf(px, c3.x, fmaf(py, c3.y, fmaf(pz, c3.z, c3.w)));
            int j = 3;
            if (s2 == best[p]) j = 2;
            if (s1 == best[p]) j = 1;
            if (s0 == best[p]) j = 0;
            cc[p] = spalc[k0 + j];
        }

        *reinterpret_cast<float4*>(obase) =
            make_float4(cc[0].x, cc[1].x, cc[2].x, cc[3].x);
        *reinterpret_cast<float4*>(obase + CR_HW) =
            make_float4(cc[0].y, cc[1].y, cc[2].y, cc[3].y);
        *reinterpret_cast<float4*>(obase + 2 * CR_HW) =
            make_float4(cc[0].z, cc[1].z, cc[2].z, cc[3].z);
    } else {
        for (int i = i0; i < npix; i++) {
            int b2 = i >> 18;
            int q2 = i & (CR_HW - 1);
            const float* pb2 = x + (size_t)b2 * 3 * CR_HW + q2;
            float px = pb2[0], py = pb2[CR_HW], pz = pb2[2 * CR_HW];
            float bestv = -FLT_MAX; int bk = 0;
            for (int k = 0; k < 64; k++) {
                float4 c = spalc[k];
                float s = fmaf(px, c.x, fmaf(py, c.y, fmaf(pz, c.z, c.w)));
                if (s > bestv) { bestv = s; bk = k; }
            }
            float4 c = spalc[bk];
            float* ob = out + (size_t)b2 * 3 * CR_HW + q2;
            ob[0] = c.x; ob[CR_HW] = c.y; ob[2 * CR_HW] = c.z;
        }
    }
}

// generic fallback (any shape / ncol) — reads palette straight from gmem
__global__ void color_reduce_generic_kernel(const float* __restrict__ x,
                                            const float* __restrict__ pal,
                                            float* __restrict__ out,
                                            int npix, int hw, int ncol)
{
    extern __shared__ float4 gpal[];
    int t = threadIdx.x;
    for (int k = t; k < ncol; k += blockDim.x) {
        float cx = pal[k * 3 + 0], cy = pal[k * 3 + 1], cz = pal[k * 3 + 2];
        gpal[k] = make_float4(cx, cy, cz, -0.5f * (cx * cx + cy * cy + cz * cz));
    }
    __syncthreads();
    int i = blockIdx.x * blockDim.x + t;
    if (i >= npix) return;
    int b = i / hw, q = i - b * hw;
    const float* pb = x + (size_t)b * 3 * (size_t)hw + q;
    float px = pb[0], py = pb[hw], pz = pb[2 * hw];
    float bestv = -FLT_MAX; int bk = 0;
    for (int k = 0; k < ncol; k++) {
        float4 c = gpal[k];
        float s = fmaf(px, c.x, fmaf(py, c.y, fmaf(pz, c.z, c.w)));
        if (s > bestv) { bestv = s; bk = k; }
    }
    float4 c = gpal[bk];
    float* ob = out + (size_t)b * 3 * (size_t)hw + q;
    ob[0] = c.x; ob[hw] = c.y; ob[2 * hw] = c.z;
}

extern "C" void kernel_launch(void* const* d_in, const int* in_sizes, int n_in,
                              void* d_out, int out_size)
{
    const float* x   = (const float*)d_in[0];
    const float* pal = (const float*)d_in[1];
    float*       out = (float*)d_out;

    int nelem = in_sizes[0];
    int ncol  = in_sizes[1] / 3;
    int npix  = nelem / 3;

    if (ncol == 64 && nelem % (3 * CR_HW) == 0) {
        // 1) build transformed palette in a device staging buffer
        prep_kernel<<<1, 64>>>(pal);

        // 2) async D2D copy into the constant banks (graph-capturable memcpy nodes)
        void* p2 = nullptr;
        void* pc = nullptr;
        cudaGetSymbolAddress(&p2, g_stage2);
        cudaGetSymbolAddress(&pc, g_stagec);
        cudaMemcpyToSymbolAsync(c_pal2, p2, sizeof(g_stage2), 0,
                                cudaMemcpyDeviceToDevice, 0);
        cudaMemcpyToSymbolAsync(c_palc, pc, sizeof(g_stagec), 0,
                                cudaMemcpyDeviceToDevice, 0);

        // 3) main kernel
        int threads = 256;
        int groups  = (npix + PPT - 1) / PPT;
        int blocks  = (groups + threads - 1) / threads;
        color_reduce_c_kernel<<<blocks, threads>>>(x, out, npix);
    } else {
        int hw = npix;
        if (nelem % (3 * CR_HW) == 0) hw = CR_HW;
        int threads = 256;
        int blocks  = (npix + threads - 1) / threads;
        color_reduce_generic_kernel<<<blocks, threads, ncol * sizeof(float4)>>>(
            x, pal, out, npix, hw, ncol);
    }
}

// round 5
// speedup vs baseline: 1.3279x; 1.0338x over previous
#include <cuda_runtime.h>
#include <cuda_bf16.h>
#include <cfloat>

// ColorReducer: out[b,:,h,w] = palette[argmin_k ||x[b,:,h,w] - palette[k]||^2]
// argmin_k ||p-c||^2 == argmax_k s_k, s_k = p.c - 0.5*||c||^2.
//
// Round-5:
//  - __constant__ palette (prep kernel -> single memcpyToSymbolAsync, capturable)
//  - fma.rn.f32x2 packed FMA (2 pixels / instruction, bit-identical to FFMA.rn)
//  - tournament argmax over groups of 4 colors; winning group recomputed with
//    identical FMA order => exact equality match, first-index tie rule.
//  - __launch_bounds__(256, 5): cap regs at 48 -> 5 blocks/SM -> ~62% occupancy
//    (round 4 was latency-limited at 45% occ / 58% issue).

#define CR_HW 262144
#define PPT 4

#define F2FMA(d, a, b, c) \
    asm("fma.rn.f32x2 %0, %1, %2, %3;" : "=l"(d) : "l"(a), "l"(b), "l"(c))
#define F2PACK(d, lo, hi) \
    asm("mov.b64 %0, {%1, %2};" : "=l"(d) : "f"(lo), "f"(hi))
#define F2UNPACK(lo, hi, v) \
    asm("mov.b64 {%0, %1}, %2;" : "=f"(lo), "=f"(hi) : "l"(v))

typedef unsigned long long ull;

struct PalConst {
    // [k][0] = {cx,cx},{cy,cy}; [k][1] = {cz,cz},{h,h}
    ulonglong2 pal2[64][2];
    float4     palc[64];
};

__constant__ __align__(16) PalConst c_pal;
__device__  __align__(16) PalConst g_stage;

__global__ void prep_kernel(const float* __restrict__ pal)
{
    int t = threadIdx.x;
    if (t < 64) {
        float cx = pal[t * 3 + 0];
        float cy = pal[t * 3 + 1];
        float cz = pal[t * 3 + 2];
        float h  = -0.5f * (cx * cx + cy * cy + cz * cz);
        ull uxx, uyy, uzz, uhh;
        F2PACK(uxx, cx, cx);
        F2PACK(uyy, cy, cy);
        F2PACK(uzz, cz, cz);
        F2PACK(uhh, h,  h);
        g_stage.pal2[t][0] = make_ulonglong2(uxx, uyy);
        g_stage.pal2[t][1] = make_ulonglong2(uzz, uhh);
        g_stage.palc[t]    = make_float4(cx, cy, cz, h);
    }
}

__global__ void __launch_bounds__(256, 5)
color_reduce_c_kernel(const float* __restrict__ x,
                      float* __restrict__ out,
                      int npix)
{
    // smem copy of compact palette (same bits as constants) for the
    // divergent-index finale + gather only.
    __shared__ float4 spalc[64];
    int t = threadIdx.x;
    if (t < 64) spalc[t] = c_pal.palc[t];
    __syncthreads();

    int gid = blockIdx.x * blockDim.x + t;
    int i0  = gid * PPT;
    if (i0 >= npix) return;

    int b = i0 >> 18;             // / CR_HW
    int q = i0 & (CR_HW - 1);

    const float* base  = x   + (size_t)b * 3 * CR_HW + q;
    float*       obase = out + (size_t)b * 3 * CR_HW + q;

    if (i0 + PPT - 1 < npix) {
        float4 pr = *reinterpret_cast<const float4*>(base);
        float4 pg = *reinterpret_cast<const float4*>(base + CR_HW);
        float4 pb = *reinterpret_cast<const float4*>(base + 2 * CR_HW);

        float rr[4] = {pr.x, pr.y, pr.z, pr.w};
        float gg[4] = {pg.x, pg.y, pg.z, pg.w};
        float bb[4] = {pb.x, pb.y, pb.z, pb.w};

        ull rp[2], gp[2], bp[2];
        F2PACK(rp[0], rr[0], rr[1]); F2PACK(rp[1], rr[2], rr[3]);
        F2PACK(gp[0], gg[0], gg[1]); F2PACK(gp[1], gg[2], gg[3]);
        F2PACK(bp[0], bb[0], bb[1]); F2PACK(bp[1], bb[2], bb[3]);

        float best[4];
        int   bgrp[4];
#pragma unroll
        for (int p = 0; p < 4; p++) { best[p] = -FLT_MAX; bgrp[p] = 0; }

#pragma unroll
        for (int g = 0; g < 16; g++) {
            ull cxx[4], cyy[4], czz[4], chh[4];
#pragma unroll
            for (int c = 0; c < 4; c++) {
                ulonglong2 v0 = c_pal.pal2[g * 4 + c][0];
                ulonglong2 v1 = c_pal.pal2[g * 4 + c][1];
                cxx[c] = v0.x; cyy[c] = v0.y; czz[c] = v1.x; chh[c] = v1.y;
            }
#pragma unroll
            for (int pp = 0; pp < 2; pp++) {   // 2 pixel pairs
                float s[4][2];
#pragma unroll
                for (int c = 0; c < 4; c++) {
                    ull sv;
                    F2FMA(sv, bp[pp], czz[c], chh[c]);
                    F2FMA(sv, gp[pp], cyy[c], sv);
                    F2FMA(sv, rp[pp], cxx[c], sv);
                    F2UNPACK(s[c][0], s[c][1], sv);
                }
#pragma unroll
                for (int half = 0; half < 2; half++) {
                    int p = 2 * pp + half;
                    float m = fmaxf(fmaxf(s[0][half], s[1][half]),
                                    fmaxf(s[2][half], s[3][half]));
                    if (m > best[p]) { best[p] = m; bgrp[p] = g; }
                }
            }
        }

        // finale: recompute winning group's 4 scores (identical FMA order ->
        // exact equality), pick first matching index, gather color from smem.
        float4 cc[4];
#pragma unroll
        for (int p = 0; p < 4; p++) {
            int k0 = bgrp[p] * 4;
            float4 c0 = spalc[k0 + 0];
            float4 c1 = spalc[k0 + 1];
            float4 c2 = spalc[k0 + 2];
            float4 c3 = spalc[k0 + 3];
            float px = rr[p], py = gg[p], pz = bb[p];
            float s0 = fmaf(px, c0.x, fmaf(py, c0.y, fmaf(pz, c0.z, c0.w)));
            float s1 = fmaf(px, c1.x, fmaf(py, c1.y, fmaf(pz, c1.z, c1.w)));
            float s2 = fmaf(px, c2.x, fmaf(py, c2.y, fmaf(pz, c2.z, c2.w)));
            float s3 = fmaf(px, c3.x, fmaf(py, c3.y, fmaf(pz, c3.z, c3.w)));
            int j = 3;
            if (s2 == best[p]) j = 2;
            if (s1 == best[p]) j = 1;
            if (s0 == best[p]) j = 0;
            cc[p] = spalc[k0 + j];
        }

        *reinterpret_cast<float4*>(obase) =
            make_float4(cc[0].x, cc[1].x, cc[2].x, cc[3].x);
        *reinterpret_cast<float4*>(obase + CR_HW) =
            make_float4(cc[0].y, cc[1].y, cc[2].y, cc[3].y);
        *reinterpret_cast<float4*>(obase + 2 * CR_HW) =
            make_float4(cc[0].z, cc[1].z, cc[2].z, cc[3].z);
    } else {
        for (int i = i0; i < npix; i++) {
            int b2 = i >> 18;
            int q2 = i & (CR_HW - 1);
            const float* pb2 = x + (size_t)b2 * 3 * CR_HW + q2;
            float px = pb2[0], py = pb2[CR_HW], pz = pb2[2 * CR_HW];
            float bestv = -FLT_MAX; int bk = 0;
            for (int k = 0; k < 64; k++) {
                float4 c = spalc[k];
                float s = fmaf(px, c.x, fmaf(py, c.y, fmaf(pz, c.z, c.w)));
                if (s > bestv) { bestv = s; bk = k; }
            }
            float4 c = spalc[bk];
            float* ob = out + (size_t)b2 * 3 * CR_HW + q2;
            ob[0] = c.x; ob[CR_HW] = c.y; ob[2 * CR_HW] = c.z;
        }
    }
}

// generic fallback (any shape / ncol)
__global__ void color_reduce_generic_kernel(const float* __restrict__ x,
                                            const float* __restrict__ pal,
                                            float* __restrict__ out,
                                            int npix, int hw, int ncol)
{
    extern __shared__ float4 gpal[];
    int t = threadIdx.x;
    for (int k = t; k < ncol; k += blockDim.x) {
        float cx = pal[k * 3 + 0], cy = pal[k * 3 + 1], cz = pal[k * 3 + 2];
        gpal[k] = make_float4(cx, cy, cz, -0.5f * (cx * cx + cy * cy + cz * cz));
    }
    __syncthreads();
    int i = blockIdx.x * blockDim.x + t;
    if (i >= npix) return;
    int b = i / hw, q = i - b * hw;
    const float* pb = x + (size_t)b * 3 * (size_t)hw + q;
    float px = pb[0], py = pb[hw], pz = pb[2 * hw];
    float bestv = -FLT_MAX; int bk = 0;
    for (int k = 0; k < ncol; k++) {
        float4 c = gpal[k];
        float s = fmaf(px, c.x, fmaf(py, c.y, fmaf(pz, c.z, c.w)));
        if (s > bestv) { bestv = s; bk = k; }
    }
    float4 c = gpal[bk];
    float* ob = out + (size_t)b * 3 * (size_t)hw + q;
    ob[0] = c.x; ob[hw] = c.y; ob[2 * hw] = c.z;
}

extern "C" void kernel_launch(void* const* d_in, const int* in_sizes, int n_in,
                              void* d_out, int out_size)
{
    const float* x   = (const float*)d_in[0];
    const float* pal = (const float*)d_in[1];
    float*       out = (float*)d_out;

    int nelem = in_sizes[0];
    int ncol  = in_sizes[1] / 3;
    int npix  = nelem / 3;

    if (ncol == 64 && nelem % (3 * CR_HW) == 0) {
        prep_kernel<<<1, 64>>>(pal);

        void* ps = nullptr;
        cudaGetSymbolAddress(&ps, g_stage);
        cudaMemcpyToSymbolAsync(c_pal, ps, sizeof(PalConst), 0,
                                cudaMemcpyDeviceToDevice, 0);

        int threads = 256;
        int groups  = (npix + PPT - 1) / PPT;
        int blocks  = (groups + threads - 1) / threads;
        color_reduce_c_kernel<<<blocks, threads>>>(x, out, npix);
    } else {
        int hw = npix;
        if (nelem % (3 * CR_HW) == 0) hw = CR_HW;
        int threads = 256;
        int blocks  = (npix + threads - 1) / threads;
        color_reduce_generic_kernel<<<blocks, threads, ncol * sizeof(float4)>>>(
            x, pal, out, npix, hw, ncol);
    }
}